// round 3
// baseline (speedup 1.0000x reference)
#include <cuda_runtime.h>
#include <cstdint>

#define T_STEPS 1024
#define BATCH   64
#define DIN     256
#define DH      256
#define G4      1024   // 4*DH
#define OUT_MAIN (T_STEPS*BATCH*DH)

// ---------------- scratch (static device globals; no allocation) ----------------
__device__ float g_Gx[(size_t)T_STEPS * BATCH * G4];   // precomputed x-part of gates
__device__ float g_WxT[DIN * G4];                      // Wx transposed [k][j]
__device__ float g_bvec[G4];                           // packed bias

// ---------------- helpers ----------------
__device__ __forceinline__ uint32_t sh_u32(const void* p) {
    return (uint32_t)__cvta_generic_to_shared(p);
}
__device__ __forceinline__ uint32_t mapa_sh(uint32_t addr, uint32_t rank) {
    uint32_t r;
    asm("mapa.shared::cluster.u32 %0, %1, %2;" : "=r"(r) : "r"(addr), "r"(rank));
    return r;
}
__device__ __forceinline__ void st_cluster_f32(uint32_t addr, float v) {
    asm volatile("st.shared::cluster.b32 [%0], %1;" :: "r"(addr), "r"(__float_as_uint(v)) : "memory");
}
__device__ __forceinline__ void mbar_init(uint32_t addr, uint32_t cnt) {
    asm volatile("mbarrier.init.shared.b64 [%0], %1;" :: "r"(addr), "r"(cnt) : "memory");
}
__device__ __forceinline__ void mbar_arrive_cluster(uint32_t mapped_addr) {
    asm volatile("mbarrier.arrive.release.cluster.shared::cluster.b64 _, [%0];"
                 :: "r"(mapped_addr) : "memory");
}
__device__ __forceinline__ void mbar_wait_cluster(uint32_t addr, uint32_t parity) {
    uint32_t done;
    asm volatile("{\n\t.reg .pred p;\n\t"
                 "mbarrier.try_wait.parity.acquire.cluster.shared::cta.b64 p, [%1], %2, 0x989680;\n\t"
                 "selp.b32 %0, 1, 0, p;\n\t}"
                 : "=r"(done) : "r"(addr), "r"(parity) : "memory");
    while (!done) {
        asm volatile("{\n\t.reg .pred p;\n\t"
                     "mbarrier.try_wait.parity.acquire.cluster.shared::cta.b64 p, [%1], %2, 0x989680;\n\t"
                     "selp.b32 %0, 1, 0, p;\n\t}"
                     : "=r"(done) : "r"(addr), "r"(parity) : "memory");
    }
}
__device__ __forceinline__ unsigned long long ffma2(unsigned long long a, unsigned long long b,
                                                    unsigned long long c) {
    unsigned long long d;
    asm("fma.rn.f32x2 %0, %1, %2, %3;" : "=l"(d) : "l"(a), "l"(b), "l"(c));
    return d;
}
__device__ __forceinline__ float2 unpack2(unsigned long long v) {
    float2 r;
    asm("mov.b64 {%0, %1}, %2;" : "=f"(r.x), "=f"(r.y) : "l"(v));
    return r;
}
__device__ __forceinline__ float sigm(float x) { return 1.f / (1.f + __expf(-x)); }
__device__ __forceinline__ float tanh_fast(float x) {
    float e = __expf(2.f * x);
    return (e - 1.f) * __frcp_rn(e + 1.f);
}

// ---------------- prep: pack Wx (k-major) + bias ----------------
__global__ void prep_kernel(const float* __restrict__ Wf, const float* __restrict__ Wi,
                            const float* __restrict__ Wg, const float* __restrict__ Wo,
                            const float* __restrict__ bF, const float* __restrict__ bI,
                            const float* __restrict__ bG, const float* __restrict__ bO)
{
    int idx = blockIdx.x * blockDim.x + threadIdx.x;
    const float* Ws[4] = {Wf, Wi, Wg, Wo};
    for (int i = idx; i < DIN * G4; i += gridDim.x * blockDim.x) {
        int k = i >> 10;
        int j = i & (G4 - 1);
        int gate = j >> 8;
        int row  = j & 255;
        g_WxT[i] = Ws[gate][row * 512 + k];
    }
    if (idx < G4) {
        int gate = idx >> 8, row = idx & 255;
        const float* bs[4] = {bF, bI, bG, bO};
        g_bvec[idx] = bs[gate][row];
    }
}

// ---------------- phase 1: Gx = X @ Wx^T + b ----------------
__global__ __launch_bounds__(256) void gemm_x_kernel(const float* __restrict__ A)
{
    __shared__ float As[8][128];
    __shared__ float Bs[8][128];

    int tid = threadIdx.x;
    int bn = blockIdx.x;
    int bm = blockIdx.y;
    int tx = tid & 15;
    int ty = tid >> 4;

    float acc[8][8];
    #pragma unroll
    for (int i = 0; i < 8; i++)
        #pragma unroll
        for (int j = 0; j < 8; j++) acc[i][j] = 0.f;

    const float* Aptr = A + (size_t)bm * 128 * DIN;
    const float* Bptr = g_WxT + bn * 128;

    int arow = tid >> 1;
    int acol = (tid & 1) << 2;
    int bkk  = tid >> 5;
    int bj   = (tid & 31) << 2;

    for (int k0 = 0; k0 < DIN; k0 += 8) {
        float4 a4 = *(const float4*)(Aptr + arow * DIN + k0 + acol);
        As[acol + 0][arow] = a4.x;
        As[acol + 1][arow] = a4.y;
        As[acol + 2][arow] = a4.z;
        As[acol + 3][arow] = a4.w;
        *(float4*)&Bs[bkk][bj] = *(const float4*)(Bptr + (size_t)(k0 + bkk) * G4 + bj);
        __syncthreads();

        #pragma unroll
        for (int kk = 0; kk < 8; kk++) {
            float4 a0 = *(const float4*)&As[kk][ty * 8];
            float4 a1 = *(const float4*)&As[kk][ty * 8 + 4];
            float4 b0 = *(const float4*)&Bs[kk][tx * 8];
            float4 b1 = *(const float4*)&Bs[kk][tx * 8 + 4];
            float af[8] = {a0.x, a0.y, a0.z, a0.w, a1.x, a1.y, a1.z, a1.w};
            float bf[8] = {b0.x, b0.y, b0.z, b0.w, b1.x, b1.y, b1.z, b1.w};
            #pragma unroll
            for (int mi = 0; mi < 8; mi++)
                #pragma unroll
                for (int ni = 0; ni < 8; ni++)
                    acc[mi][ni] += af[mi] * bf[ni];
        }
        __syncthreads();
    }

    int jbase = bn * 128 + tx * 8;
    float4 bb0 = *(const float4*)&g_bvec[jbase];
    float4 bb1 = *(const float4*)&g_bvec[jbase + 4];
    #pragma unroll
    for (int mi = 0; mi < 8; mi++) {
        size_t r = (size_t)bm * 128 + ty * 8 + mi;
        float* op = g_Gx + r * G4 + jbase;
        float4 o0 = make_float4(acc[mi][0] + bb0.x, acc[mi][1] + bb0.y,
                                acc[mi][2] + bb0.z, acc[mi][3] + bb0.w);
        float4 o1 = make_float4(acc[mi][4] + bb1.x, acc[mi][5] + bb1.y,
                                acc[mi][6] + bb1.z, acc[mi][7] + bb1.w);
        *(float4*)op = o0;
        *(float4*)(op + 4) = o1;
    }
}

// ---------------- phase 2: persistent recurrent kernel (8-CTA clusters + DSMEM) ----------------
// 16 clusters (batch groups of 4) x 8 CTAs (32 h cols each). h exchanged via DSMEM push:
// producers store into all 8 peers' double-buffered smem + remote mbarrier arrive.
__global__ __launch_bounds__(256, 1) __cluster_dims__(8, 1, 1)
void lstm_kernel(const float* __restrict__ Wf, const float* __restrict__ Wi,
                 const float* __restrict__ Wg, const float* __restrict__ Wo,
                 const float* __restrict__ h0, const float* __restrict__ c0,
                 float* __restrict__ out, int out_size)
{
    __shared__ alignas(16) float sh_h[2][4 * DH];          // ping-pong h: [4 batches][256]
    __shared__ alignas(8) unsigned long long sh_bar[2];    // mbarriers (parity ping-pong)

    int tid = threadIdx.x;
    int grp = blockIdx.x >> 3;    // batch group 0..15
    int cg  = blockIdx.x & 7;     // cluster rank / h-slice 0..7
    int hh  = tid >> 3;           // 0..31
    int kg  = tid & 7;            // 0..7

    int hglob = cg * 32 + hh;
    const float* Wp[4] = {Wf + hglob * 512 + 256, Wi + hglob * 512 + 256,
                          Wg + hglob * 512 + 256, Wo + hglob * 512 + 256};

    // weights: k-chunks (c*8+kg)*4, each ulonglong2 = 2 packed f32x2 pairs
    ulonglong2 w2[4][8];
    #pragma unroll
    for (int g = 0; g < 4; g++)
        #pragma unroll
        for (int c = 0; c < 8; c++)
            w2[g][c] = *(const ulonglong2*)(Wp[g] + (c * 8 + kg) * 4);

    // init: h0 slice into buffer 0; barriers count = 8 (one arrive per cluster CTA)
    ((float4*)sh_h[0])[tid] = ((const float4*)(h0 + (size_t)grp * 4 * DH))[tid];
    uint32_t bar_base = sh_u32(sh_bar);
    if (tid == 0) {
        mbar_init(bar_base + 0, 8);
        mbar_init(bar_base + 8, 8);
    }
    __syncthreads();
    asm volatile("barrier.cluster.arrive.aligned;" ::: "memory");
    asm volatile("barrier.cluster.wait.aligned;" ::: "memory");

    // cell ownership: lanes kg<4 hold cell (batch kg, col hglob)
    int bglob = grp * 4 + kg;
    float cval = (kg < 4) ? c0[bglob * DH + hglob] : 0.f;

    // precompute peer push addresses (value for (batch kg, col hglob))
    uint32_t h_base = sh_u32(sh_h);
    uint32_t my_off = (uint32_t)(kg * DH + hglob) * 4u;
    uint32_t peer_data[8];
    #pragma unroll
    for (int r = 0; r < 8; r++) peer_data[r] = mapa_sh(h_base, r) + my_off;
    uint32_t bar_peer = (tid < 8) ? mapa_sh(bar_base, tid) : 0u;

    int ph0 = 0, ph1 = 0;

    #pragma unroll 1
    for (int t = 0; t < T_STEPS; t++) {
        // prefetch Gx for this step before the wait (hides DRAM latency)
        float gx[4];
        if (kg < 4) {
            const float* gp = g_Gx + (size_t)t * (BATCH * G4) + (size_t)bglob * G4 + hglob;
            #pragma unroll
            for (int g = 0; g < 4; g++) gx[g] = __ldcs(gp + g * 256);
        }

        // wait for h[t] (buffer t&1) — all 8 producer arrivals
        if (t > 0) {
            if (t & 1) { mbar_wait_cluster(bar_base + 8, ph1); ph1 ^= 1; }
            else       { mbar_wait_cluster(bar_base + 0, ph0); ph0 ^= 1; }
        }

        // packed dot products: acc[g][b] accumulates k-pairs as f32x2
        const ulonglong2* hbuf = (const ulonglong2*)sh_h[t & 1];
        unsigned long long acc[4][4];
        #pragma unroll
        for (int g = 0; g < 4; g++)
            #pragma unroll
            for (int b = 0; b < 4; b++) acc[g][b] = 0ull;

        #pragma unroll
        for (int c = 0; c < 8; c++) {
            #pragma unroll
            for (int b = 0; b < 4; b++) {
                ulonglong2 h2 = hbuf[b * 64 + c * 8 + kg];
                #pragma unroll
                for (int g = 0; g < 4; g++) {
                    acc[g][b] = ffma2(w2[g][c].x, h2.x, acc[g][b]);
                    acc[g][b] = ffma2(w2[g][c].y, h2.y, acc[g][b]);
                }
            }
        }

        // collapse pairs, then butterfly-reduce over kg (lane bits 0..2)
        float accf[4][4];
        #pragma unroll
        for (int g = 0; g < 4; g++)
            #pragma unroll
            for (int b = 0; b < 4; b++) {
                float2 p = unpack2(acc[g][b]);
                accf[g][b] = p.x + p.y;
            }
        #pragma unroll
        for (int m = 1; m < 8; m <<= 1)
            #pragma unroll
            for (int g = 0; g < 4; g++)
                #pragma unroll
                for (int b = 0; b < 4; b++)
                    accf[g][b] += __shfl_xor_sync(0xffffffffu, accf[g][b], m);

        // cell update + DSMEM push of h(t+1) into all 8 peers' other buffer
        if (kg < 4) {
            float fg = sigm(accf[0][kg] + gx[0]);
            float ig = sigm(accf[1][kg] + gx[1]);
            float gg = tanh_fast(accf[2][kg] + gx[2]);
            float og = sigm(accf[3][kg] + gx[3]);
            cval = fg * cval + ig * gg;
            float hn = og * tanh_fast(cval);

            uint32_t boff = (uint32_t)((t + 1) & 1) * (4 * DH * 4);
            #pragma unroll
            for (int r = 0; r < 8; r++) st_cluster_f32(peer_data[r] + boff, hn);

            int idx = bglob * DH + hglob;
            out[(size_t)t * (BATCH * DH) + idx] = hn;
            if (t == T_STEPS - 1 && out_size > OUT_MAIN) {
                out[(size_t)OUT_MAIN + idx] = hn;
                out[(size_t)OUT_MAIN + BATCH * DH + idx] = cval;
            }
        }
        __syncthreads();   // all this CTA's remote stores done (happens-before for release)

        // one arrive per peer: releases this CTA's pushed h values
        if (tid < 8) mbar_arrive_cluster(bar_peer + (uint32_t)(((t + 1) & 1) * 8));
    }

    asm volatile("barrier.cluster.arrive.aligned;" ::: "memory");
    asm volatile("barrier.cluster.wait.aligned;" ::: "memory");
}

// ---------------- launch ----------------
extern "C" void kernel_launch(void* const* d_in, const int* in_sizes, int n_in,
                              void* d_out, int out_size)
{
    const float* inputs = (const float*)d_in[0];
    const float* h0     = (const float*)d_in[1];
    const float* c0     = (const float*)d_in[2];
    const float* Wf     = (const float*)d_in[3];
    const float* bF     = (const float*)d_in[4];
    const float* Wi     = (const float*)d_in[5];
    const float* bI     = (const float*)d_in[6];
    const float* Wg     = (const float*)d_in[7];
    const float* bG     = (const float*)d_in[8];
    const float* Wo     = (const float*)d_in[9];
    const float* bO     = (const float*)d_in[10];
    float* out = (float*)d_out;

    prep_kernel<<<256, 256>>>(Wf, Wi, Wg, Wo, bF, bI, bG, bO);
    gemm_x_kernel<<<dim3(8, 512), 256>>>(inputs);
    lstm_kernel<<<128, 256>>>(Wf, Wi, Wg, Wo, h0, c0, out, out_size);
}

// round 6
// speedup vs baseline: 1.0982x; 1.0982x over previous
#include <cuda_runtime.h>
#include <cstdint>

#define T_STEPS 1024
#define BATCH   64
#define DIN     256
#define DH      256
#define G4      1024   // 4*DH
#define OUT_MAIN (T_STEPS*BATCH*DH)

// ---------------- scratch (static device globals; no allocation) ----------------
__device__ float g_Gx[(size_t)T_STEPS * BATCH * G4];   // precomputed x-part of gates
__device__ float g_WxT[DIN * G4];                      // Wx transposed [k][j]
__device__ float g_bvec[G4];                           // packed bias
__device__ float g_hbuf[2][BATCH * DH];                // double-buffered h
__device__ unsigned int g_flags[16 * 16];              // per-group: 8 producer flags

// ---------------- primitives ----------------
__device__ __forceinline__ void st_release(unsigned int* p, unsigned int v) {
    asm volatile("st.release.gpu.u32 [%0], %1;" :: "l"(p), "r"(v) : "memory");
}
__device__ __forceinline__ unsigned int ld_acquire(const unsigned int* p) {
    unsigned int v;
    asm volatile("ld.acquire.gpu.u32 %0, [%1];" : "=r"(v) : "l"(p) : "memory");
    return v;
}
__device__ __forceinline__ float4 ldcg4(const float4* p) {
    float4 v;
    asm volatile("ld.global.cg.v4.f32 {%0,%1,%2,%3}, [%4];"
                 : "=f"(v.x), "=f"(v.y), "=f"(v.z), "=f"(v.w) : "l"(p) : "memory");
    return v;
}
__device__ __forceinline__ unsigned long long ffma2(unsigned long long a, unsigned long long b,
                                                    unsigned long long c) {
    unsigned long long d;
    asm("fma.rn.f32x2 %0, %1, %2, %3;" : "=l"(d) : "l"(a), "l"(b), "l"(c));
    return d;
}
__device__ __forceinline__ float2 unpack2(unsigned long long v) {
    float2 r;
    asm("mov.b64 {%0, %1}, %2;" : "=f"(r.x), "=f"(r.y) : "l"(v));
    return r;
}
__device__ __forceinline__ float sigm(float x) { return 1.f / (1.f + __expf(-x)); }
__device__ __forceinline__ float tanh_fast(float x) {
    float e = __expf(2.f * x);
    return (e - 1.f) * __frcp_rn(e + 1.f);
}

// ---------------- prep: pack Wx (k-major) + bias ----------------
__global__ void prep_kernel(const float* __restrict__ Wf, const float* __restrict__ Wi,
                            const float* __restrict__ Wg, const float* __restrict__ Wo,
                            const float* __restrict__ bF, const float* __restrict__ bI,
                            const float* __restrict__ bG, const float* __restrict__ bO)
{
    int idx = blockIdx.x * blockDim.x + threadIdx.x;
    const float* Ws[4] = {Wf, Wi, Wg, Wo};
    for (int i = idx; i < DIN * G4; i += gridDim.x * blockDim.x) {
        int k = i >> 10;
        int j = i & (G4 - 1);
        int gate = j >> 8;
        int row  = j & 255;
        g_WxT[i] = Ws[gate][row * 512 + k];
    }
    if (idx < G4) {
        int gate = idx >> 8, row = idx & 255;
        const float* bs[4] = {bF, bI, bG, bO};
        g_bvec[idx] = bs[gate][row];
    }
}

// ---------------- init: h0 -> buffer, reset flags (every graph replay) ----------------
__global__ void init_kernel(const float* __restrict__ h0)
{
    int i = blockIdx.x * blockDim.x + threadIdx.x;
    if (i < BATCH * DH) g_hbuf[0][i] = h0[i];
    if (i < 16 * 16)    g_flags[i] = 0;
}

// ---------------- phase 1: Gx = X @ Wx^T + b   (65536 x 1024 x 256 SGEMM) ----------------
__global__ __launch_bounds__(256) void gemm_x_kernel(const float* __restrict__ A)
{
    __shared__ float As[8][128];
    __shared__ float Bs[8][128];

    int tid = threadIdx.x;
    int bn = blockIdx.x;
    int bm = blockIdx.y;
    int tx = tid & 15;
    int ty = tid >> 4;

    float acc[8][8];
    #pragma unroll
    for (int i = 0; i < 8; i++)
        #pragma unroll
        for (int j = 0; j < 8; j++) acc[i][j] = 0.f;

    const float* Aptr = A + (size_t)bm * 128 * DIN;
    const float* Bptr = g_WxT + bn * 128;

    int arow = tid >> 1;
    int acol = (tid & 1) << 2;
    int bkk  = tid >> 5;
    int bj   = (tid & 31) << 2;

    for (int k0 = 0; k0 < DIN; k0 += 8) {
        float4 a4 = *(const float4*)(Aptr + arow * DIN + k0 + acol);
        As[acol + 0][arow] = a4.x;
        As[acol + 1][arow] = a4.y;
        As[acol + 2][arow] = a4.z;
        As[acol + 3][arow] = a4.w;
        *(float4*)&Bs[bkk][bj] = *(const float4*)(Bptr + (size_t)(k0 + bkk) * G4 + bj);
        __syncthreads();

        #pragma unroll
        for (int kk = 0; kk < 8; kk++) {
            float4 a0 = *(const float4*)&As[kk][ty * 8];
            float4 a1 = *(const float4*)&As[kk][ty * 8 + 4];
            float4 b0 = *(const float4*)&Bs[kk][tx * 8];
            float4 b1 = *(const float4*)&Bs[kk][tx * 8 + 4];
            float af[8] = {a0.x, a0.y, a0.z, a0.w, a1.x, a1.y, a1.z, a1.w};
            float bf[8] = {b0.x, b0.y, b0.z, b0.w, b1.x, b1.y, b1.z, b1.w};
            #pragma unroll
            for (int mi = 0; mi < 8; mi++)
                #pragma unroll
                for (int ni = 0; ni < 8; ni++)
                    acc[mi][ni] += af[mi] * bf[ni];
        }
        __syncthreads();
    }

    int jbase = bn * 128 + tx * 8;
    float4 bb0 = *(const float4*)&g_bvec[jbase];
    float4 bb1 = *(const float4*)&g_bvec[jbase + 4];
    #pragma unroll
    for (int mi = 0; mi < 8; mi++) {
        size_t r = (size_t)bm * 128 + ty * 8 + mi;
        float* op = g_Gx + r * G4 + jbase;
        float4 o0 = make_float4(acc[mi][0] + bb0.x, acc[mi][1] + bb0.y,
                                acc[mi][2] + bb0.z, acc[mi][3] + bb0.w);
        float4 o1 = make_float4(acc[mi][4] + bb1.x, acc[mi][5] + bb1.y,
                                acc[mi][6] + bb1.z, acc[mi][7] + bb1.w);
        *(float4*)op = o0;
        *(float4*)(op + 4) = o1;
    }
}

// ---------------- phase 2: persistent recurrent kernel ----------------
// 128 CTAs = 16 batch-groups (4 batches) x 8 h-slices (32 h cols, all 4 gates).
// 512 threads: hh = tid>>4 (h col), kg = tid&15 (16-float k-chunk, strided).
// f32x2 packed FMAs (128 FFMA2/thread), butterfly reduce over kg (4 rounds).
__global__ __launch_bounds__(512, 1) void lstm_kernel(
    const float* __restrict__ Wf, const float* __restrict__ Wi,
    const float* __restrict__ Wg, const float* __restrict__ Wo,
    const float* __restrict__ c0, float* __restrict__ out, int out_size)
{
    __shared__ alignas(16) float sh_h[4 * DH];   // h slice: [4 batches][256]

    int tid = threadIdx.x;
    int grp = blockIdx.x >> 3;    // 0..15 batch group (4 batches)
    int cg  = blockIdx.x & 7;     // 0..7  h-slice (32 h cols)
    int hh  = tid >> 4;           // 0..31
    int kg  = tid & 15;           // 0..15

    int hglob = cg * 32 + hh;
    const float* Wp[4] = {Wf + hglob * 512 + 256, Wi + hglob * 512 + 256,
                          Wg + hglob * 512 + 256, Wo + hglob * 512 + 256};

    // weights: k float4-chunks c*16+kg (c=0..3), as ulonglong2 = 2 f32x2 pairs
    ulonglong2 w2[4][4];
    #pragma unroll
    for (int g = 0; g < 4; g++)
        #pragma unroll
        for (int c = 0; c < 4; c++)
            w2[g][c] = *(const ulonglong2*)(Wp[g] + (c * 16 + kg) * 4);

    // cell ownership: lanes kg<4 hold cell (batch kg, col hglob)
    int bglob = grp * 4 + kg;     // valid when kg < 4
    float cval = (kg < 4) ? c0[bglob * DH + hglob] : 0.f;

    unsigned int* flags = &g_flags[grp * 16];
    const size_t hoff = (size_t)grp * 4 * DH;

    #pragma unroll 1
    for (int t = 0; t < T_STEPS; t++) {
        // prefetch Gx for this step (independent of flags; hides DRAM latency)
        float gx[4];
        if (kg < 4) {
            const float* gp = g_Gx + (size_t)t * (BATCH * G4) + (size_t)bglob * G4 + hglob;
            #pragma unroll
            for (int g = 0; g < 4; g++) gx[g] = __ldcs(gp + g * 256);
        }

        // wait for all 8 producers of this group to publish h[t]
        if (tid < 8) {
            while (ld_acquire(&flags[tid]) < (unsigned)t) { }
        }
        __syncthreads();

        // stage h[t] (4 batches x 256) into smem; .cg bypasses stale L1
        if (tid < 256) {
            const float4* hsrc = (const float4*)(g_hbuf[t & 1] + hoff);
            ((float4*)sh_h)[tid] = ldcg4(hsrc + tid);
        }
        __syncthreads();

        // packed dots: acc[gate][batch] over this thread's 16 k's (8 ffma2 each)
        const ulonglong2* hbuf = (const ulonglong2*)sh_h;
        unsigned long long acc[4][4];
        #pragma unroll
        for (int g = 0; g < 4; g++)
            #pragma unroll
            for (int b = 0; b < 4; b++) acc[g][b] = 0ull;

        #pragma unroll
        for (int c = 0; c < 4; c++) {
            #pragma unroll
            for (int b = 0; b < 4; b++) {
                ulonglong2 h2 = hbuf[b * 64 + c * 16 + kg];
                #pragma unroll
                for (int g = 0; g < 4; g++) {
                    acc[g][b] = ffma2(w2[g][c].x, h2.x, acc[g][b]);
                    acc[g][b] = ffma2(w2[g][c].y, h2.y, acc[g][b]);
                }
            }
        }

        // collapse pairs, butterfly reduce over kg (lane bits 0..3)
        float accf[4][4];
        #pragma unroll
        for (int g = 0; g < 4; g++)
            #pragma unroll
            for (int b = 0; b < 4; b++) {
                float2 p = unpack2(acc[g][b]);
                accf[g][b] = p.x + p.y;
            }
        #pragma unroll
        for (int m = 1; m < 16; m <<= 1)
            #pragma unroll
            for (int g = 0; g < 4; g++)
                #pragma unroll
                for (int b = 0; b < 4; b++)
                    accf[g][b] += __shfl_xor_sync(0xffffffffu, accf[g][b], m);

        // cell update: lane kg<4 handles batch kg
        if (kg < 4) {
            float fg = sigm(accf[0][kg] + gx[0]);
            float ig = sigm(accf[1][kg] + gx[1]);
            float gg = tanh_fast(accf[2][kg] + gx[2]);
            float og = sigm(accf[3][kg] + gx[3]);
            cval = fg * cval + ig * gg;
            float hn = og * tanh_fast(cval);
            int idx = bglob * DH + hglob;
            g_hbuf[(t + 1) & 1][idx] = hn;
            out[(size_t)t * (BATCH * DH) + idx] = hn;
            if (t == T_STEPS - 1 && out_size > OUT_MAIN) {
                out[(size_t)OUT_MAIN + idx] = hn;
                out[(size_t)OUT_MAIN + BATCH * DH + idx] = cval;
            }
        }
        __syncthreads();

        // publish: all this CTA's h stores ordered before the flag (bar + release)
        if (tid == 0) st_release(&flags[cg], (unsigned)(t + 1));
    }
}

// ---------------- launch ----------------
extern "C" void kernel_launch(void* const* d_in, const int* in_sizes, int n_in,
                              void* d_out, int out_size)
{
    const float* inputs = (const float*)d_in[0];
    const float* h0     = (const float*)d_in[1];
    const float* c0     = (const float*)d_in[2];
    const float* Wf     = (const float*)d_in[3];
    const float* bF     = (const float*)d_in[4];
    const float* Wi     = (const float*)d_in[5];
    const float* bI     = (const float*)d_in[6];
    const float* Wg     = (const float*)d_in[7];
    const float* bG     = (const float*)d_in[8];
    const float* Wo     = (const float*)d_in[9];
    const float* bO     = (const float*)d_in[10];
    float* out = (float*)d_out;

    prep_kernel<<<256, 256>>>(Wf, Wi, Wg, Wo, bF, bI, bG, bO);
    init_kernel<<<64, 256>>>(h0);
    gemm_x_kernel<<<dim3(8, 512), 256>>>(inputs);
    lstm_kernel<<<128, 512>>>(Wf, Wi, Wg, Wo, c0, out, out_size);
}

// round 7
// speedup vs baseline: 1.1518x; 1.0488x over previous
#include <cuda_runtime.h>
#include <cstdint>

#define T_STEPS 1024
#define BATCH   64
#define DIN     256
#define DH      256
#define G4      1024   // 4*DH
#define OUT_MAIN (T_STEPS*BATCH*DH)

// ---------------- scratch (static device globals; no allocation) ----------------
__device__ float g_Gx[(size_t)T_STEPS * BATCH * G4];   // precomputed x-part of gates
__device__ float g_WxT[DIN * G4];                      // Wx transposed [k][j]
__device__ float g_bvec[G4];                           // packed bias
__device__ float g_hbuf[2][BATCH * DH];                // double-buffered h
__device__ unsigned int g_flags[16 * 16];              // per-group: 8 producer flags

// ---------------- primitives ----------------
__device__ __forceinline__ void st_release(unsigned int* p, unsigned int v) {
    asm volatile("st.release.gpu.u32 [%0], %1;" :: "l"(p), "r"(v) : "memory");
}
__device__ __forceinline__ unsigned int ld_acquire(const unsigned int* p) {
    unsigned int v;
    asm volatile("ld.acquire.gpu.u32 %0, [%1];" : "=r"(v) : "l"(p) : "memory");
    return v;
}
__device__ __forceinline__ float4 ldcg4(const float4* p) {
    float4 v;
    asm volatile("ld.global.cg.v4.f32 {%0,%1,%2,%3}, [%4];"
                 : "=f"(v.x), "=f"(v.y), "=f"(v.z), "=f"(v.w) : "l"(p) : "memory");
    return v;
}
__device__ __forceinline__ unsigned long long ffma2(unsigned long long a, unsigned long long b,
                                                    unsigned long long c) {
    unsigned long long d;
    asm("fma.rn.f32x2 %0, %1, %2, %3;" : "=l"(d) : "l"(a), "l"(b), "l"(c));
    return d;
}
__device__ __forceinline__ float2 unpack2(unsigned long long v) {
    float2 r;
    asm("mov.b64 {%0, %1}, %2;" : "=f"(r.x), "=f"(r.y) : "l"(v));
    return r;
}
__device__ __forceinline__ float sigm(float x) { return 1.f / (1.f + __expf(-x)); }
__device__ __forceinline__ float tanh_fast(float x) {
    float e = __expf(2.f * x);
    return (e - 1.f) * __frcp_rn(e + 1.f);
}

// ---------------- prep: pack Wx (k-major) + bias ----------------
__global__ void prep_kernel(const float* __restrict__ Wf, const float* __restrict__ Wi,
                            const float* __restrict__ Wg, const float* __restrict__ Wo,
                            const float* __restrict__ bF, const float* __restrict__ bI,
                            const float* __restrict__ bG, const float* __restrict__ bO)
{
    int idx = blockIdx.x * blockDim.x + threadIdx.x;
    const float* Ws[4] = {Wf, Wi, Wg, Wo};
    for (int i = idx; i < DIN * G4; i += gridDim.x * blockDim.x) {
        int k = i >> 10;
        int j = i & (G4 - 1);
        int gate = j >> 8;
        int row  = j & 255;
        g_WxT[i] = Ws[gate][row * 512 + k];
    }
    if (idx < G4) {
        int gate = idx >> 8, row = idx & 255;
        const float* bs[4] = {bF, bI, bG, bO};
        g_bvec[idx] = bs[gate][row];
    }
}

// ---------------- init: h0 -> buffer, reset flags (every graph replay) ----------------
__global__ void init_kernel(const float* __restrict__ h0)
{
    int i = blockIdx.x * blockDim.x + threadIdx.x;
    if (i < BATCH * DH) g_hbuf[0][i] = h0[i];
    if (i < 16 * 16)    g_flags[i] = 0;
}

// ---------------- phase 1: Gx = X @ Wx^T + b   (65536 x 1024 x 256 SGEMM) ----------------
__global__ __launch_bounds__(256) void gemm_x_kernel(const float* __restrict__ A)
{
    __shared__ float As[8][128];
    __shared__ float Bs[8][128];

    int tid = threadIdx.x;
    int bn = blockIdx.x;
    int bm = blockIdx.y;
    int tx = tid & 15;
    int ty = tid >> 4;

    float acc[8][8];
    #pragma unroll
    for (int i = 0; i < 8; i++)
        #pragma unroll
        for (int j = 0; j < 8; j++) acc[i][j] = 0.f;

    const float* Aptr = A + (size_t)bm * 128 * DIN;
    const float* Bptr = g_WxT + bn * 128;

    int arow = tid >> 1;
    int acol = (tid & 1) << 2;
    int bkk  = tid >> 5;
    int bj   = (tid & 31) << 2;

    for (int k0 = 0; k0 < DIN; k0 += 8) {
        float4 a4 = *(const float4*)(Aptr + arow * DIN + k0 + acol);
        As[acol + 0][arow] = a4.x;
        As[acol + 1][arow] = a4.y;
        As[acol + 2][arow] = a4.z;
        As[acol + 3][arow] = a4.w;
        *(float4*)&Bs[bkk][bj] = *(const float4*)(Bptr + (size_t)(k0 + bkk) * G4 + bj);
        __syncthreads();

        #pragma unroll
        for (int kk = 0; kk < 8; kk++) {
            float4 a0 = *(const float4*)&As[kk][ty * 8];
            float4 a1 = *(const float4*)&As[kk][ty * 8 + 4];
            float4 b0 = *(const float4*)&Bs[kk][tx * 8];
            float4 b1 = *(const float4*)&Bs[kk][tx * 8 + 4];
            float af[8] = {a0.x, a0.y, a0.z, a0.w, a1.x, a1.y, a1.z, a1.w};
            float bf[8] = {b0.x, b0.y, b0.z, b0.w, b1.x, b1.y, b1.z, b1.w};
            #pragma unroll
            for (int mi = 0; mi < 8; mi++)
                #pragma unroll
                for (int ni = 0; ni < 8; ni++)
                    acc[mi][ni] += af[mi] * bf[ni];
        }
        __syncthreads();
    }

    int jbase = bn * 128 + tx * 8;
    float4 bb0 = *(const float4*)&g_bvec[jbase];
    float4 bb1 = *(const float4*)&g_bvec[jbase + 4];
    #pragma unroll
    for (int mi = 0; mi < 8; mi++) {
        size_t r = (size_t)bm * 128 + ty * 8 + mi;
        float* op = g_Gx + r * G4 + jbase;
        float4 o0 = make_float4(acc[mi][0] + bb0.x, acc[mi][1] + bb0.y,
                                acc[mi][2] + bb0.z, acc[mi][3] + bb0.w);
        float4 o1 = make_float4(acc[mi][4] + bb1.x, acc[mi][5] + bb1.y,
                                acc[mi][6] + bb1.z, acc[mi][7] + bb1.w);
        *(float4*)op = o0;
        *(float4*)(op + 4) = o1;
    }
}

// ---------------- phase 2: persistent recurrent kernel ----------------
// 128 CTAs = 16 batch-groups (4 batches) x 8 h-slices (32 h cols, all 4 gates).
// 256 threads: hh = tid>>3 (h col), kg = tid&7 (k-split 8, strided chunks).
// f32x2 packed FMAs (256 FFMA2/thread); FOLD reduction over kg: values halve
// per round (16 shfl/thread vs 48 for the full butterfly).
__global__ __launch_bounds__(256, 1) void lstm_kernel(
    const float* __restrict__ Wf, const float* __restrict__ Wi,
    const float* __restrict__ Wg, const float* __restrict__ Wo,
    const float* __restrict__ c0, float* __restrict__ out, int out_size)
{
    __shared__ alignas(16) float sh_h[4 * DH];   // h slice: [4 batches][256]

    int tid = threadIdx.x;
    int grp = blockIdx.x >> 3;    // 0..15 batch group (4 batches)
    int cg  = blockIdx.x & 7;     // 0..7  h-slice (32 h cols)
    int hh  = tid >> 3;           // 0..31
    int kg  = tid & 7;            // 0..7
    int bit2 = (kg >> 2) & 1, bit1 = (kg >> 1) & 1, bit0 = kg & 1;

    int hglob = cg * 32 + hh;
    const float* Wp[4] = {Wf + hglob * 512 + 256, Wi + hglob * 512 + 256,
                          Wg + hglob * 512 + 256, Wo + hglob * 512 + 256};

    // weights: k-chunks (c*8+kg)*4 (strided), each ulonglong2 = 2 f32x2 pairs
    ulonglong2 w2[4][8];
    #pragma unroll
    for (int g = 0; g < 4; g++)
        #pragma unroll
        for (int c = 0; c < 8; c++)
            w2[g][c] = *(const ulonglong2*)(Wp[g] + (c * 8 + kg) * 4);

    // cell ownership: lanes bit0==0 hold cell for batch kg>>1
    int bown  = kg >> 1;                 // 0..3 (meaningful when bit0==0)
    int bglob = grp * 4 + bown;
    float cval = (bit0 == 0) ? c0[bglob * DH + hglob] : 0.f;

    unsigned int* flags = &g_flags[grp * 16];
    const size_t hoff = (size_t)grp * 4 * DH;

    #pragma unroll 1
    for (int t = 0; t < T_STEPS; t++) {
        // prefetch Gx for this step (independent of flags; hides DRAM latency)
        float gx[4];
        if (bit0 == 0) {
            const float* gp = g_Gx + (size_t)t * (BATCH * G4) + (size_t)bglob * G4 + hglob;
            #pragma unroll
            for (int g = 0; g < 4; g++) gx[g] = __ldcs(gp + g * 256);
        }

        // wait for all 8 producers of this group to publish h[t]
        if (tid < 8) {
            while (ld_acquire(&flags[tid]) < (unsigned)t) { }
        }
        __syncthreads();

        // stage h[t] (4 batches x 256) into smem; .cg bypasses stale L1
        const float4* hsrc = (const float4*)(g_hbuf[t & 1] + hoff);
        ((float4*)sh_h)[tid] = ldcg4(hsrc + tid);
        __syncthreads();

        // packed dots: acc[gate][batch] over this thread's 32 k's (16 ffma2 each)
        const ulonglong2* hbuf = (const ulonglong2*)sh_h;
        unsigned long long acc[4][4];
        #pragma unroll
        for (int g = 0; g < 4; g++)
            #pragma unroll
            for (int b = 0; b < 4; b++) acc[g][b] = 0ull;

        #pragma unroll
        for (int c = 0; c < 8; c++) {
            #pragma unroll
            for (int b = 0; b < 4; b++) {
                ulonglong2 h2 = hbuf[b * 64 + c * 8 + kg];
                #pragma unroll
                for (int g = 0; g < 4; g++) {
                    acc[g][b] = ffma2(w2[g][c].x, h2.x, acc[g][b]);
                    acc[g][b] = ffma2(w2[g][c].y, h2.y, acc[g][b]);
                }
            }
        }

        // collapse f32x2 pairs
        float accf[4][4];
        #pragma unroll
        for (int g = 0; g < 4; g++)
            #pragma unroll
            for (int b = 0; b < 4; b++) {
                float2 p = unpack2(acc[g][b]);
                accf[g][b] = p.x + p.y;
            }

        // FOLD reduction over kg (values halve each round; 16 shfl total).
        // Round 1 (xor 4): keep batches {bit2*2, bit2*2+1}, send the others.
        float r1[4][2];
        #pragma unroll
        for (int g = 0; g < 4; g++)
            #pragma unroll
            for (int j = 0; j < 2; j++) {
                float snd = accf[g][(1 - bit2) * 2 + j];
                float rcv = __shfl_xor_sync(0xffffffffu, snd, 4);
                r1[g][j] = accf[g][bit2 * 2 + j] + rcv;
            }
        // Round 2 (xor 2): keep batch j==bit1. Final batch = bit2*2+bit1 = kg>>1.
        float r2[4];
        #pragma unroll
        for (int g = 0; g < 4; g++) {
            float snd = r1[g][1 - bit1];
            float rcv = __shfl_xor_sync(0xffffffffu, snd, 2);
            r2[g] = r1[g][bit1] + rcv;
        }
        // Round 3 (xor 1): keep gates {2*bit0, 2*bit0+1}, send the others.
        float r3[2];
        #pragma unroll
        for (int j = 0; j < 2; j++) {
            float snd = r2[2 * (1 - bit0) + j];
            float rcv = __shfl_xor_sync(0xffffffffu, snd, 1);
            r3[j] = r2[2 * bit0 + j] + rcv;
        }
        // Final exchange (xor 1): obtain the other gate pair.
        float o0 = __shfl_xor_sync(0xffffffffu, r3[0], 1);
        float o1 = __shfl_xor_sync(0xffffffffu, r3[1], 1);

        // cell update: lanes bit0==0 handle batch kg>>1 (r3 = gates f,i; o = g,o)
        if (bit0 == 0) {
            float fg = sigm(r3[0] + gx[0]);
            float ig = sigm(r3[1] + gx[1]);
            float gg = tanh_fast(o0 + gx[2]);
            float og = sigm(o1 + gx[3]);
            cval = fg * cval + ig * gg;
            float hn = og * tanh_fast(cval);
            int idx = bglob * DH + hglob;
            g_hbuf[(t + 1) & 1][idx] = hn;
            out[(size_t)t * (BATCH * DH) + idx] = hn;
            if (t == T_STEPS - 1 && out_size > OUT_MAIN) {
                out[(size_t)OUT_MAIN + idx] = hn;
                out[(size_t)OUT_MAIN + BATCH * DH + idx] = cval;
            }
        }
        __syncthreads();

        // publish: all this CTA's h stores ordered before the flag (bar + release)
        if (tid == 0) st_release(&flags[cg], (unsigned)(t + 1));
    }
}

// ---------------- launch ----------------
extern "C" void kernel_launch(void* const* d_in, const int* in_sizes, int n_in,
                              void* d_out, int out_size)
{
    const float* inputs = (const float*)d_in[0];
    const float* h0     = (const float*)d_in[1];
    const float* c0     = (const float*)d_in[2];
    const float* Wf     = (const float*)d_in[3];
    const float* bF     = (const float*)d_in[4];
    const float* Wi     = (const float*)d_in[5];
    const float* bI     = (const float*)d_in[6];
    const float* Wg     = (const float*)d_in[7];
    const float* bG     = (const float*)d_in[8];
    const float* Wo     = (const float*)d_in[9];
    const float* bO     = (const float*)d_in[10];
    float* out = (float*)d_out;

    prep_kernel<<<256, 256>>>(Wf, Wi, Wg, Wo, bF, bI, bG, bO);
    init_kernel<<<64, 256>>>(h0);
    gemm_x_kernel<<<dim3(8, 512), 256>>>(inputs);
    lstm_kernel<<<128, 256>>>(Wf, Wi, Wg, Wo, c0, out, out_size);
}

// round 8
// speedup vs baseline: 1.5022x; 1.3043x over previous
#include <cuda_runtime.h>
#include <cstdint>

#define T_STEPS 1024
#define BATCH   64
#define DIN     256
#define DH      256
#define G4      1024   // 4*DH
#define OUT_MAIN (T_STEPS*BATCH*DH)

// ---------------- scratch (static device globals; no allocation) ----------------
__device__ float g_Gx[(size_t)T_STEPS * BATCH * G4];   // precomputed x-part of gates
__device__ float g_WxT[DIN * G4];                      // Wx transposed [k][j]
__device__ float g_bvec[G4];                           // packed bias
__device__ float g_hbuf[2][BATCH * DH];                // double-buffered h
__device__ unsigned int g_flags[16 * 16];              // per-group: 8 producer flags

// ---------------- primitives ----------------
__device__ __forceinline__ void st_release(unsigned int* p, unsigned int v) {
    asm volatile("st.release.gpu.u32 [%0], %1;" :: "l"(p), "r"(v) : "memory");
}
__device__ __forceinline__ unsigned int ld_acquire(const unsigned int* p) {
    unsigned int v;
    asm volatile("ld.acquire.gpu.u32 %0, [%1];" : "=r"(v) : "l"(p) : "memory");
    return v;
}
__device__ __forceinline__ float4 ldcg4(const float4* p) {
    float4 v;
    asm volatile("ld.global.cg.v4.f32 {%0,%1,%2,%3}, [%4];"
                 : "=f"(v.x), "=f"(v.y), "=f"(v.z), "=f"(v.w) : "l"(p) : "memory");
    return v;
}
__device__ __forceinline__ float sigm(float x) { return 1.f / (1.f + __expf(-x)); }
__device__ __forceinline__ float tanh_fast(float x) {
    float e = __expf(2.f * x);
    return (e - 1.f) * __frcp_rn(e + 1.f);
}

// ---------------- prep: pack Wx (k-major) + bias ----------------
__global__ void prep_kernel(const float* __restrict__ Wf, const float* __restrict__ Wi,
                            const float* __restrict__ Wg, const float* __restrict__ Wo,
                            const float* __restrict__ bF, const float* __restrict__ bI,
                            const float* __restrict__ bG, const float* __restrict__ bO)
{
    int idx = blockIdx.x * blockDim.x + threadIdx.x;
    const float* Ws[4] = {Wf, Wi, Wg, Wo};
    for (int i = idx; i < DIN * G4; i += gridDim.x * blockDim.x) {
        int k = i >> 10;
        int j = i & (G4 - 1);
        int gate = j >> 8;
        int row  = j & 255;
        g_WxT[i] = Ws[gate][row * 512 + k];
    }
    if (idx < G4) {
        int gate = idx >> 8, row = idx & 255;
        const float* bs[4] = {bF, bI, bG, bO};
        g_bvec[idx] = bs[gate][row];
    }
}

// ---------------- init: h0 -> buffer, reset flags (every graph replay) ----------------
__global__ void init_kernel(const float* __restrict__ h0)
{
    int i = blockIdx.x * blockDim.x + threadIdx.x;
    if (i < BATCH * DH) g_hbuf[0][i] = h0[i];
    if (i < 16 * 16)    g_flags[i] = 0;
}

// ---------------- phase 1: Gx = X @ Wx^T + b   (65536 x 1024 x 256 SGEMM) ----------------
__global__ __launch_bounds__(256) void gemm_x_kernel(const float* __restrict__ A)
{
    __shared__ float As[8][128];
    __shared__ float Bs[8][128];

    int tid = threadIdx.x;
    int bn = blockIdx.x;
    int bm = blockIdx.y;
    int tx = tid & 15;
    int ty = tid >> 4;

    float acc[8][8];
    #pragma unroll
    for (int i = 0; i < 8; i++)
        #pragma unroll
        for (int j = 0; j < 8; j++) acc[i][j] = 0.f;

    const float* Aptr = A + (size_t)bm * 128 * DIN;
    const float* Bptr = g_WxT + bn * 128;

    int arow = tid >> 1;
    int acol = (tid & 1) << 2;
    int bkk  = tid >> 5;
    int bj   = (tid & 31) << 2;

    for (int k0 = 0; k0 < DIN; k0 += 8) {
        float4 a4 = *(const float4*)(Aptr + arow * DIN + k0 + acol);
        As[acol + 0][arow] = a4.x;
        As[acol + 1][arow] = a4.y;
        As[acol + 2][arow] = a4.z;
        As[acol + 3][arow] = a4.w;
        *(float4*)&Bs[bkk][bj] = *(const float4*)(Bptr + (size_t)(k0 + bkk) * G4 + bj);
        __syncthreads();

        #pragma unroll
        for (int kk = 0; kk < 8; kk++) {
            float4 a0 = *(const float4*)&As[kk][ty * 8];
            float4 a1 = *(const float4*)&As[kk][ty * 8 + 4];
            float4 b0 = *(const float4*)&Bs[kk][tx * 8];
            float4 b1 = *(const float4*)&Bs[kk][tx * 8 + 4];
            float af[8] = {a0.x, a0.y, a0.z, a0.w, a1.x, a1.y, a1.z, a1.w};
            float bf[8] = {b0.x, b0.y, b0.z, b0.w, b1.x, b1.y, b1.z, b1.w};
            #pragma unroll
            for (int mi = 0; mi < 8; mi++)
                #pragma unroll
                for (int ni = 0; ni < 8; ni++)
                    acc[mi][ni] += af[mi] * bf[ni];
        }
        __syncthreads();
    }

    int jbase = bn * 128 + tx * 8;
    float4 bb0 = *(const float4*)&g_bvec[jbase];
    float4 bb1 = *(const float4*)&g_bvec[jbase + 4];
    #pragma unroll
    for (int mi = 0; mi < 8; mi++) {
        size_t r = (size_t)bm * 128 + ty * 8 + mi;
        float* op = g_Gx + r * G4 + jbase;
        float4 o0 = make_float4(acc[mi][0] + bb0.x, acc[mi][1] + bb0.y,
                                acc[mi][2] + bb0.z, acc[mi][3] + bb0.w);
        float4 o1 = make_float4(acc[mi][4] + bb1.x, acc[mi][5] + bb1.y,
                                acc[mi][6] + bb1.z, acc[mi][7] + bb1.w);
        *(float4*)op = o0;
        *(float4*)(op + 4) = o1;
    }
}

// ---------------- phase 2: persistent recurrent kernel ----------------
// 128 CTAs = 16 batch-groups (4 batches) x 8 h-slices (32 h cols, all 4 gates).
// 512 threads (16 warps): hh = tid>>4 (h col), kg = tid&15 (16-float k-chunk set,
// strided). Scalar FFMA (256/thread); FOLD reduction over kg (15 shfl) + 3-shfl
// gate gather. Cell owner: lanes kg%4==0, batch kg>>2.
__global__ __launch_bounds__(512, 1) void lstm_kernel(
    const float* __restrict__ Wf, const float* __restrict__ Wi,
    const float* __restrict__ Wg, const float* __restrict__ Wo,
    const float* __restrict__ c0, float* __restrict__ out, int out_size)
{
    __shared__ alignas(16) float4 sh_h4[4 * 64];   // h slice: [4 batches][256]

    int tid = threadIdx.x;
    int grp = blockIdx.x >> 3;    // 0..15 batch group (4 batches)
    int cg  = blockIdx.x & 7;     // 0..7  h-slice (32 h cols)
    int hh  = tid >> 4;           // 0..31
    int kg  = tid & 15;           // 0..15
    int b3 = (kg >> 3) & 1, b2 = (kg >> 2) & 1, b1 = (kg >> 1) & 1, b0 = kg & 1;

    int hglob = cg * 32 + hh;
    const float* Wp[4] = {Wf + hglob * 512 + 256, Wi + hglob * 512 + 256,
                          Wg + hglob * 512 + 256, Wo + hglob * 512 + 256};

    // weights: 4 gates x 4 strided float4 chunks (float4-index c*16+kg)
    float4 w4[4][4];
    #pragma unroll
    for (int g = 0; g < 4; g++)
        #pragma unroll
        for (int c = 0; c < 4; c++)
            w4[g][c] = *(const float4*)(Wp[g] + (c * 16 + kg) * 4);

    // cell ownership: lanes kg%4==0 hold cell for batch kg>>2
    bool owner = (kg & 3) == 0;
    int bown   = kg >> 2;
    int bglob  = grp * 4 + bown;
    float cval = owner ? c0[bglob * DH + hglob] : 0.f;

    unsigned int* flags = &g_flags[grp * 16];
    const size_t hoff = (size_t)grp * 4 * DH;

    #pragma unroll 1
    for (int t = 0; t < T_STEPS; t++) {
        // prefetch Gx for this step (independent of flags; hides DRAM latency)
        float gx[4];
        if (owner) {
            const float* gp = g_Gx + (size_t)t * (BATCH * G4) + (size_t)bglob * G4 + hglob;
            #pragma unroll
            for (int g = 0; g < 4; g++) gx[g] = __ldcs(gp + g * 256);
        }

        // wait for all 8 producers of this group to publish h[t]
        if (tid < 8) {
            while (ld_acquire(&flags[tid]) < (unsigned)t) { }
        }
        __syncthreads();

        // stage h[t] (4 batches x 256) into smem; .cg bypasses stale L1
        if (tid < 256) {
            const float4* hsrc = (const float4*)(g_hbuf[t & 1] + hoff);
            sh_h4[tid] = ldcg4(hsrc + tid);
        }
        __syncthreads();

        // scalar-FFMA dots: acc[gate][batch] over this thread's 16 k's
        float acc[4][4];
        #pragma unroll
        for (int g = 0; g < 4; g++)
            #pragma unroll
            for (int b = 0; b < 4; b++) acc[g][b] = 0.f;

        #pragma unroll
        for (int c = 0; c < 4; c++) {
            #pragma unroll
            for (int b = 0; b < 4; b++) {
                float4 h4 = sh_h4[b * 64 + c * 16 + kg];
                #pragma unroll
                for (int g = 0; g < 4; g++) {
                    acc[g][b] += w4[g][c].x * h4.x;
                    acc[g][b] += w4[g][c].y * h4.y;
                    acc[g][b] += w4[g][c].z * h4.z;
                    acc[g][b] += w4[g][c].w * h4.w;
                }
            }
        }

        // FOLD reduction over kg (values halve each round; 15 shfl + 3 gather).
        // Round 1 (xor 8): fold batches 4 -> 2 (keep pair selected by b3).
        float r1[4][2];
        #pragma unroll
        for (int g = 0; g < 4; g++)
            #pragma unroll
            for (int j = 0; j < 2; j++) {
                float keep = b3 ? acc[g][2 + j] : acc[g][j];
                float snd  = b3 ? acc[g][j]     : acc[g][2 + j];
                r1[g][j] = keep + __shfl_xor_sync(0xffffffffu, snd, 8);
            }
        // Round 2 (xor 4): fold batches 2 -> 1 (keep b2). Batch = 2*b3+b2 = kg>>2.
        float r2[4];
        #pragma unroll
        for (int g = 0; g < 4; g++) {
            float keep = b2 ? r1[g][1] : r1[g][0];
            float snd  = b2 ? r1[g][0] : r1[g][1];
            r2[g] = keep + __shfl_xor_sync(0xffffffffu, snd, 4);
        }
        // Round 3 (xor 2): fold gates 4 -> 2 (keep pair selected by b1).
        float r3[2];
        #pragma unroll
        for (int j = 0; j < 2; j++) {
            float keep = b1 ? r2[2 + j] : r2[j];
            float snd  = b1 ? r2[j]     : r2[2 + j];
            r3[j] = keep + __shfl_xor_sync(0xffffffffu, snd, 2);
        }
        // Round 4 (xor 1): fold gates 2 -> 1 (keep b0). Gate = 2*b1+b0 = kg&3.
        {
            float keep = b0 ? r3[1] : r3[0];
            float snd  = b0 ? r3[0] : r3[1];
            r3[0] = keep + __shfl_xor_sync(0xffffffffu, snd, 1);
        }
        float r4 = r3[0];
        // Gather gates 1..3 to the owner lane (kg%4==0): lanes kg^1,kg^2,kg^3.
        float q1 = __shfl_xor_sync(0xffffffffu, r4, 1);
        float q2 = __shfl_xor_sync(0xffffffffu, r4, 2);
        float q3 = __shfl_xor_sync(0xffffffffu, r4, 3);

        // cell update on owner lanes
        if (owner) {
            float fg = sigm(r4 + gx[0]);
            float ig = sigm(q1 + gx[1]);
            float gg = tanh_fast(q2 + gx[2]);
            float og = sigm(q3 + gx[3]);
            cval = fg * cval + ig * gg;
            float hn = og * tanh_fast(cval);
            int idx = bglob * DH + hglob;
            g_hbuf[(t + 1) & 1][idx] = hn;
            out[(size_t)t * (BATCH * DH) + idx] = hn;
            if (t == T_STEPS - 1 && out_size > OUT_MAIN) {
                out[(size_t)OUT_MAIN + idx] = hn;
                out[(size_t)OUT_MAIN + BATCH * DH + idx] = cval;
            }
        }
        __syncthreads();

        // publish: all this CTA's h stores ordered before the flag (bar + release)
        if (tid == 0) st_release(&flags[cg], (unsigned)(t + 1));
    }
}

// ---------------- launch ----------------
extern "C" void kernel_launch(void* const* d_in, const int* in_sizes, int n_in,
                              void* d_out, int out_size)
{
    const float* inputs = (const float*)d_in[0];
    const float* h0     = (const float*)d_in[1];
    const float* c0     = (const float*)d_in[2];
    const float* Wf     = (const float*)d_in[3];
    const float* bF     = (const float*)d_in[4];
    const float* Wi     = (const float*)d_in[5];
    const float* bI     = (const float*)d_in[6];
    const float* Wg     = (const float*)d_in[7];
    const float* bG     = (const float*)d_in[8];
    const float* Wo     = (const float*)d_in[9];
    const float* bO     = (const float*)d_in[10];
    float* out = (float*)d_out;

    prep_kernel<<<256, 256>>>(Wf, Wi, Wg, Wo, bF, bI, bG, bO);
    init_kernel<<<64, 256>>>(h0);
    gemm_x_kernel<<<dim3(8, 512), 256>>>(inputs);
    lstm_kernel<<<128, 512>>>(Wf, Wi, Wg, Wo, c0, out, out_size);
}

// round 9
// speedup vs baseline: 1.5288x; 1.0177x over previous
#include <cuda_runtime.h>
#include <cstdint>

#define T_STEPS 1024
#define BATCH   64
#define DIN     256
#define DH      256
#define G4      1024   // 4*DH
#define OUT_MAIN (T_STEPS*BATCH*DH)

// ---------------- scratch (static device globals; no allocation) ----------------
__device__ float g_Gx[(size_t)T_STEPS * BATCH * G4];   // precomputed x-part of gates
__device__ float g_WxT[DIN * G4];                      // Wx transposed [k][j]
__device__ float g_bvec[G4];                           // packed bias
__device__ float g_hT[2][16][DH][4];                   // double-buffered h, transposed [k][batch], tf32-rounded
__device__ unsigned int g_flags[16 * 16];              // per-group: 8 producer flags

// ---------------- primitives ----------------
__device__ __forceinline__ void st_release(unsigned int* p, unsigned int v) {
    asm volatile("st.release.gpu.u32 [%0], %1;" :: "l"(p), "r"(v) : "memory");
}
__device__ __forceinline__ unsigned int ld_acquire(const unsigned int* p) {
    unsigned int v;
    asm volatile("ld.acquire.gpu.u32 %0, [%1];" : "=r"(v) : "l"(p) : "memory");
    return v;
}
__device__ __forceinline__ float4 ldcg4(const float4* p) {
    float4 v;
    asm volatile("ld.global.cg.v4.f32 {%0,%1,%2,%3}, [%4];"
                 : "=f"(v.x), "=f"(v.y), "=f"(v.z), "=f"(v.w) : "l"(p) : "memory");
    return v;
}
__device__ __forceinline__ uint32_t to_tf32(float f) {
    uint32_t r;
    asm("cvt.rna.tf32.f32 %0, %1;" : "=r"(r) : "f"(f));
    return r;
}
__device__ __forceinline__ void mma_tf32(float& d0, float& d1, float& d2, float& d3,
                                         uint32_t a0, uint32_t a1, uint32_t a2, uint32_t a3,
                                         uint32_t b0, uint32_t b1) {
    asm volatile("mma.sync.aligned.m16n8k8.row.col.f32.tf32.tf32.f32 "
                 "{%0,%1,%2,%3}, {%4,%5,%6,%7}, {%8,%9}, {%0,%1,%2,%3};"
                 : "+f"(d0), "+f"(d1), "+f"(d2), "+f"(d3)
                 : "r"(a0), "r"(a1), "r"(a2), "r"(a3), "r"(b0), "r"(b1));
}
__device__ __forceinline__ float sigm(float x) { return 1.f / (1.f + __expf(-x)); }
__device__ __forceinline__ float tanh_fast(float x) {
    float e = __expf(2.f * x);
    return (e - 1.f) * __frcp_rn(e + 1.f);
}

// ---------------- prep: pack Wx (k-major) + bias ----------------
__global__ void prep_kernel(const float* __restrict__ Wf, const float* __restrict__ Wi,
                            const float* __restrict__ Wg, const float* __restrict__ Wo,
                            const float* __restrict__ bF, const float* __restrict__ bI,
                            const float* __restrict__ bG, const float* __restrict__ bO)
{
    int idx = blockIdx.x * blockDim.x + threadIdx.x;
    const float* Ws[4] = {Wf, Wi, Wg, Wo};
    for (int i = idx; i < DIN * G4; i += gridDim.x * blockDim.x) {
        int k = i >> 10;
        int j = i & (G4 - 1);
        int gate = j >> 8;
        int row  = j & 255;
        g_WxT[i] = Ws[gate][row * 512 + k];
    }
    if (idx < G4) {
        int gate = idx >> 8, row = idx & 255;
        const float* bs[4] = {bF, bI, bG, bO};
        g_bvec[idx] = bs[gate][row];
    }
}

// ---------------- init: h0 -> transposed tf32 buffer 0, reset flags ----------------
__global__ void init_kernel(const float* __restrict__ h0)
{
    int i = blockIdx.x * blockDim.x + threadIdx.x;
    if (i < BATCH * DH) {
        int bb = i >> 8;          // batch 0..63
        int k  = i & 255;         // h index
        g_hT[0][bb >> 2][k][bb & 3] = __uint_as_float(to_tf32(h0[bb * DH + k]));
    }
    if (i < 16 * 16) g_flags[i] = 0;
}

// ---------------- phase 1: Gx = X @ Wx^T + b   (65536 x 1024 x 256 SGEMM) ----------------
__global__ __launch_bounds__(256) void gemm_x_kernel(const float* __restrict__ A)
{
    __shared__ float As[8][128];
    __shared__ float Bs[8][128];

    int tid = threadIdx.x;
    int bn = blockIdx.x;
    int bm = blockIdx.y;
    int tx = tid & 15;
    int ty = tid >> 4;

    float acc[8][8];
    #pragma unroll
    for (int i = 0; i < 8; i++)
        #pragma unroll
        for (int j = 0; j < 8; j++) acc[i][j] = 0.f;

    const float* Aptr = A + (size_t)bm * 128 * DIN;
    const float* Bptr = g_WxT + bn * 128;

    int arow = tid >> 1;
    int acol = (tid & 1) << 2;
    int bkk  = tid >> 5;
    int bj   = (tid & 31) << 2;

    for (int k0 = 0; k0 < DIN; k0 += 8) {
        float4 a4 = *(const float4*)(Aptr + arow * DIN + k0 + acol);
        As[acol + 0][arow] = a4.x;
        As[acol + 1][arow] = a4.y;
        As[acol + 2][arow] = a4.z;
        As[acol + 3][arow] = a4.w;
        *(float4*)&Bs[bkk][bj] = *(const float4*)(Bptr + (size_t)(k0 + bkk) * G4 + bj);
        __syncthreads();

        #pragma unroll
        for (int kk = 0; kk < 8; kk++) {
            float4 a0 = *(const float4*)&As[kk][ty * 8];
            float4 a1 = *(const float4*)&As[kk][ty * 8 + 4];
            float4 b0 = *(const float4*)&Bs[kk][tx * 8];
            float4 b1 = *(const float4*)&Bs[kk][tx * 8 + 4];
            float af[8] = {a0.x, a0.y, a0.z, a0.w, a1.x, a1.y, a1.z, a1.w};
            float bf[8] = {b0.x, b0.y, b0.z, b0.w, b1.x, b1.y, b1.z, b1.w};
            #pragma unroll
            for (int mi = 0; mi < 8; mi++)
                #pragma unroll
                for (int ni = 0; ni < 8; ni++)
                    acc[mi][ni] += af[mi] * bf[ni];
        }
        __syncthreads();
    }

    int jbase = bn * 128 + tx * 8;
    float4 bb0 = *(const float4*)&g_bvec[jbase];
    float4 bb1 = *(const float4*)&g_bvec[jbase + 4];
    #pragma unroll
    for (int mi = 0; mi < 8; mi++) {
        size_t r = (size_t)bm * 128 + ty * 8 + mi;
        float* op = g_Gx + r * G4 + jbase;
        float4 o0 = make_float4(acc[mi][0] + bb0.x, acc[mi][1] + bb0.y,
                                acc[mi][2] + bb0.z, acc[mi][3] + bb0.w);
        float4 o1 = make_float4(acc[mi][4] + bb1.x, acc[mi][5] + bb1.y,
                                acc[mi][6] + bb1.z, acc[mi][7] + bb1.w);
        *(float4*)op = o0;
        *(float4*)(op + 4) = o1;
    }
}

// ---------------- phase 2: persistent recurrent kernel (tensor-core tf32 MMA) ----------------
// 128 CTAs = 16 batch-groups (4 batches) x 8 h-slices (32 h cols x 4 gates = 128 gate rows).
// 256 threads = 8 warps; warp w owns m-tile w (16 gate rows), full k=256 (32 chained
// m16n8k8 tf32 MMAs, weights as A-fragments resident in registers). Gate row r = hh*4+g.
// h exchanged transposed (hT[k][batch], tf32-rounded by producer).
__global__ __launch_bounds__(256, 1) void lstm_kernel(
    const float* __restrict__ Wf, const float* __restrict__ Wi,
    const float* __restrict__ Wg, const float* __restrict__ Wo,
    const float* __restrict__ c0, float* __restrict__ out, int out_size)
{
    __shared__ alignas(16) float4 hT_sm4[DH];     // staged hT: [256 k][4 batch] (float4 row)
    __shared__ float D_sm[128][9];                // gates [gate_row][batch], padded

    int tid  = threadIdx.x;
    int lane = tid & 31;
    int mt   = tid >> 5;          // warp = m-tile 0..7
    int grp  = blockIdx.x >> 3;   // batch group 0..15
    int cg   = blockIdx.x & 7;    // h-slice 0..7

    // ---- load A fragments (weights, tf32) once: r = mt*16 + row_off, gate = row_off&3 ----
    int row_off = lane >> 2;            // 0..7
    int colk    = lane & 3;             // k within tile
    int g_th    = row_off & 3;          // this thread's gate (same for all its frags)
    const float* Wsel = (g_th == 0) ? Wf : (g_th == 1) ? Wi : (g_th == 2) ? Wg : Wo;
    int hh0 = mt * 4 + (row_off >> 2);  // h col for a0/a2
    int hh1 = hh0 + 2;                  // h col for a1/a3 (row+8)
    const float* p0 = Wsel + (cg * 32 + hh0) * 512 + 256;
    const float* p1 = Wsel + (cg * 32 + hh1) * 512 + 256;

    uint32_t wA[32][4];
    #pragma unroll
    for (int kt = 0; kt < 32; kt++) {
        int k0 = kt * 8;
        wA[kt][0] = to_tf32(p0[k0 + colk]);
        wA[kt][1] = to_tf32(p1[k0 + colk]);
        wA[kt][2] = to_tf32(p0[k0 + colk + 4]);
        wA[kt][3] = to_tf32(p1[k0 + colk + 4]);
    }

    // ---- cell ownership: tid<128, batch = tid&3, h col = tid>>2 ----
    int bloc  = tid & 3;
    int hh    = tid >> 2;
    int bglob = grp * 4 + bloc;
    int hglob = cg * 32 + hh;
    float cval = (tid < 128) ? c0[bglob * DH + hglob] : 0.f;

    // ---- B-fragment smem index (conflict-free: lanes 0..15 hit distinct banks) ----
    int bcol  = lane >> 2;              // batch col 0..7; >=4 unused
    bool bval = bcol < 4;
    int bidx  = (lane & 3) * 4 + (bval ? bcol : 0);

    unsigned int* flags = &g_flags[grp * 16];
    const float4* hT_src = (const float4*)&g_hT[0][grp][0][0];
    const float4* hT_src1 = (const float4*)&g_hT[1][grp][0][0];
    float* hT_dst0 = &g_hT[0][grp][hglob][bloc];
    float* hT_dst1 = &g_hT[1][grp][hglob][bloc];

    #pragma unroll 1
    for (int t = 0; t < T_STEPS; t++) {
        // prefetch Gx for this step (independent of flags; hides DRAM latency)
        float gx0, gx1, gx2, gx3;
        if (tid < 128) {
            const float* gp = g_Gx + (size_t)t * (BATCH * G4) + (size_t)bglob * G4 + hglob;
            gx0 = __ldcs(gp);
            gx1 = __ldcs(gp + 256);
            gx2 = __ldcs(gp + 512);
            gx3 = __ldcs(gp + 768);
        }

        // wait for all 8 producers of this group to publish h[t]
        if (tid < 8) {
            while (ld_acquire(&flags[tid]) < (unsigned)t) { }
        }
        __syncthreads();

        // stage hT[t] (256 k x 4 batch) into smem; .cg bypasses stale L1
        hT_sm4[tid] = ldcg4(((t & 1) ? hT_src1 : hT_src) + tid);
        __syncthreads();

        // tensor MMA: D[16 gate rows x 4 batches] per warp, k=256 in 32 chained steps
        float d0 = 0.f, d1 = 0.f, d2 = 0.f, d3 = 0.f;
        const float* hTf = (const float*)hT_sm4;
        #pragma unroll
        for (int kt = 0; kt < 32; kt++) {
            uint32_t b0 = 0u, b1 = 0u;
            if (bval) {
                b0 = __float_as_uint(hTf[kt * 32 + bidx]);
                b1 = __float_as_uint(hTf[kt * 32 + 16 + bidx]);
            }
            mma_tf32(d0, d1, d2, d3, wA[kt][0], wA[kt][1], wA[kt][2], wA[kt][3], b0, b1);
        }

        // write D cols 0..3 (batches) to smem
        int r0 = mt * 16 + (lane >> 2);
        int cc = lane & 3;
        if (cc < 2) {
            D_sm[r0][2 * cc]         = d0;
            D_sm[r0][2 * cc + 1]     = d1;
            D_sm[r0 + 8][2 * cc]     = d2;
            D_sm[r0 + 8][2 * cc + 1] = d3;
        }
        __syncthreads();

        // cell update: thread (hh, bloc); gates at rows hh*4+g
        if (tid < 128) {
            float fg = sigm(D_sm[hh * 4 + 0][bloc] + gx0);
            float ig = sigm(D_sm[hh * 4 + 1][bloc] + gx1);
            float gg = tanh_fast(D_sm[hh * 4 + 2][bloc] + gx2);
            float og = sigm(D_sm[hh * 4 + 3][bloc] + gx3);
            cval = fg * cval + ig * gg;
            float hn = og * tanh_fast(cval);
            // publish tf32-rounded h for next step's MMA
            float hn_tf = __uint_as_float(to_tf32(hn));
            if ((t + 1) & 1) *hT_dst1 = hn_tf; else *hT_dst0 = hn_tf;
            int idx = bglob * DH + hglob;
            out[(size_t)t * (BATCH * DH) + idx] = hn;
            if (t == T_STEPS - 1 && out_size > OUT_MAIN) {
                out[(size_t)OUT_MAIN + idx] = hn;
                out[(size_t)OUT_MAIN + BATCH * DH + idx] = cval;
            }
        }
        __syncthreads();

        // publish: all this CTA's hT stores ordered before the flag (bar + release)
        if (tid == 0) st_release(&flags[cg], (unsigned)(t + 1));
    }
}

// ---------------- launch ----------------
extern "C" void kernel_launch(void* const* d_in, const int* in_sizes, int n_in,
                              void* d_out, int out_size)
{
    const float* inputs = (const float*)d_in[0];
    const float* h0     = (const float*)d_in[1];
    const float* c0     = (const float*)d_in[2];
    const float* Wf     = (const float*)d_in[3];
    const float* bF     = (const float*)d_in[4];
    const float* Wi     = (const float*)d_in[5];
    const float* bI     = (const float*)d_in[6];
    const float* Wg     = (const float*)d_in[7];
    const float* bG     = (const float*)d_in[8];
    const float* Wo     = (const float*)d_in[9];
    const float* bO     = (const float*)d_in[10];
    float* out = (float*)d_out;

    prep_kernel<<<256, 256>>>(Wf, Wi, Wg, Wo, bF, bI, bG, bO);
    init_kernel<<<64, 256>>>(h0);
    gemm_x_kernel<<<dim3(8, 512), 256>>>(inputs);
    lstm_kernel<<<128, 256>>>(Wf, Wi, Wg, Wo, c0, out, out_size);
}